// round 1
// baseline (speedup 1.0000x reference)
#include <cuda_runtime.h>
#include <cstddef>

// Problem constants: B=2, S=512, H=256, A=128
#define BB 2
#define SS 512
#define HH 256
#define AA 128

// Scratch (device globals; no allocs allowed)
__device__ float g_s[BB * SS];       // raw scores s[b,j]
__device__ float g_w[BB * SS];       // e_j * am_j  (softmax numerator, masked)
__device__ float g_scale[BB * SS];   // am_i / C_i  (per-row scale)
__device__ float g_T[BB * 8 * HH];   // tile sums for the a-prefix (8 tiles of 64)

// ---------------------------------------------------------------------------
// Kernel 1: s[b,j] = sum_a query[a] * tanh( sum_h x[b,j,h] * w_a[h,a] )
// 4 rows per block, 128 threads (one per a-column).
// ---------------------------------------------------------------------------
__global__ __launch_bounds__(128) void k_score(
    const float* __restrict__ x, const float* __restrict__ w_a,
    const float* __restrict__ query)
{
    __shared__ float xs[4 * HH];       // 4 rows of x (contiguous)
    __shared__ float red[4][128];
    const int tid = threadIdx.x;
    const int r0  = blockIdx.x * 4;    // global row index (b*S + j)

    // load 4 contiguous rows of x (1024 floats) via float4
    const float4* xin = reinterpret_cast<const float4*>(x + (size_t)r0 * HH);
    float4* xs4 = reinterpret_cast<float4*>(xs);
    xs4[tid]       = xin[tid];
    xs4[tid + 128] = xin[tid + 128];
    __syncthreads();

    float acc0 = 0.f, acc1 = 0.f, acc2 = 0.f, acc3 = 0.f;
#pragma unroll 8
    for (int h = 0; h < HH; ++h) {
        const float wa = w_a[h * AA + tid];   // coalesced across threads
        acc0 += xs[0 * HH + h] * wa;
        acc1 += xs[1 * HH + h] * wa;
        acc2 += xs[2 * HH + h] * wa;
        acc3 += xs[3 * HH + h] * wa;
    }
    const float q = query[tid];
    red[0][tid] = q * tanhf(acc0);
    red[1][tid] = q * tanhf(acc1);
    red[2][tid] = q * tanhf(acc2);
    red[3][tid] = q * tanhf(acc3);
    __syncthreads();

    // 4 warps each reduce one row's 128 partials
    const int w = tid >> 5, l = tid & 31;
    float v = red[w][l] + red[w][l + 32] + red[w][l + 64] + red[w][l + 96];
#pragma unroll
    for (int o = 16; o > 0; o >>= 1) v += __shfl_down_sync(0xffffffffu, v, o);
    if (l == 0) g_s[r0 + w] = v;
}

// ---------------------------------------------------------------------------
// Kernel 2: per-batch scan.  e_j = exp(s_j - max), C_i = prefix-sum(e).
// Emits g_w[b,j] = e_j*am_j  and  g_scale[b,i] = am_i / C_i.
// One block per batch, 512 threads.
// ---------------------------------------------------------------------------
__global__ __launch_bounds__(512) void k_scan(const int* __restrict__ amask)
{
    const int b = blockIdx.x, tid = threadIdx.x;
    __shared__ float sh[SS];
    __shared__ float red[SS];

    const float sv = g_s[b * SS + tid];

    // block max
    red[tid] = sv; __syncthreads();
#pragma unroll
    for (int o = 256; o > 0; o >>= 1) {
        if (tid < o) red[tid] = fmaxf(red[tid], red[tid + o]);
        __syncthreads();
    }
    const float M = red[0];
    const float e = expf(sv - M);

    // Hillis-Steele inclusive scan of e
    sh[tid] = e; __syncthreads();
#pragma unroll
    for (int o = 1; o < SS; o <<= 1) {
        const float t = (tid >= o) ? sh[tid - o] : 0.f;
        __syncthreads();
        sh[tid] += t;
        __syncthreads();
    }
    const float C  = sh[tid];
    const int   am = amask[b * SS + tid];
    g_w[b * SS + tid]     = am ? e : 0.f;
    g_scale[b * SS + tid] = am ? (1.f / C) : 0.f;
}

// ---------------------------------------------------------------------------
// Kernel 3: write d (B,S,S) rows, AND compute the 8 per-tile partial sums
// T[b,t,h] = sum_{j in tile t} w_j * x[b,j,h]  (tiles of 64).
// grid = (520, B):  x<512 -> d-row writer; x>=512 -> tile-sum block.
// ---------------------------------------------------------------------------
__global__ __launch_bounds__(256) void k_dwrite(
    const float* __restrict__ x, float* __restrict__ d_out)
{
    const int b = blockIdx.y, tid = threadIdx.x;

    if (blockIdx.x < SS) {
        const int i  = blockIdx.x;
        const float sc = g_scale[b * SS + i];
        const float2 w2 = reinterpret_cast<const float2*>(g_w + b * SS)[tid];
        const int j0 = tid * 2;
        float2 o;
        o.x = (j0     <= i) ? w2.x * sc : 0.f;
        o.y = (j0 + 1 <= i) ? w2.y * sc : 0.f;
        reinterpret_cast<float2*>(d_out + (size_t)(b * SS + i) * SS)[tid] = o;
    } else {
        const int t = blockIdx.x - SS;          // 0..7
        __shared__ float ws[64];
        if (tid < 64) ws[tid] = g_w[b * SS + t * 64 + tid];
        __syncthreads();
        float acc = 0.f;
        const float* xp = x + ((size_t)(b * SS + t * 64)) * HH + tid;
#pragma unroll 8
        for (int jj = 0; jj < 64; ++jj) acc += ws[jj] * xp[(size_t)jj * HH];
        g_T[(b * 8 + t) * HH + tid] = acc;
    }
}

// ---------------------------------------------------------------------------
// Kernel 4: a[b,i,h] = scale[b,i] * ( base(tile) + local prefix of w_j*x[b,j,h] ).
// grid = (8, B), 256 threads (one per h).
// ---------------------------------------------------------------------------
__global__ __launch_bounds__(256) void k_awrite(
    const float* __restrict__ x, float* __restrict__ a_out)
{
    const int b = blockIdx.y, t = blockIdx.x, tid = threadIdx.x;
    __shared__ float ws[64], scs[64];
    if (tid < 64) {
        ws[tid]  = g_w[b * SS + t * 64 + tid];
        scs[tid] = g_scale[b * SS + t * 64 + tid];
    }
    __syncthreads();

    float acc = 0.f;
    for (int tp = 0; tp < t; ++tp) acc += g_T[(b * 8 + tp) * HH + tid];

    const float* xp = x     + ((size_t)(b * SS + t * 64)) * HH + tid;
    float*       ap = a_out + ((size_t)(b * SS + t * 64)) * HH + tid;
#pragma unroll 4
    for (int jj = 0; jj < 64; ++jj) {
        acc += ws[jj] * xp[(size_t)jj * HH];
        ap[(size_t)jj * HH] = acc * scs[jj];
    }
}

// ---------------------------------------------------------------------------
extern "C" void kernel_launch(void* const* d_in, const int* in_sizes, int n_in,
                              void* d_out, int out_size)
{
    const float* x     = (const float*)d_in[0];   // (B,S,H)
    const int*   amask = (const int*)  d_in[1];   // (B,S)
    const float* w_a   = (const float*)d_in[2];   // (H,A)
    const float* query = (const float*)d_in[3];   // (A,)

    float* out   = (float*)d_out;
    float* a_out = out;                                // (B,S,H) first
    float* dd    = out + (size_t)BB * SS * HH;         // (B,S,S) second

    k_score<<<(BB * SS) / 4, 128>>>(x, w_a, query);
    k_scan<<<BB, SS>>>(amask);
    k_dwrite<<<dim3(SS + 8, BB), 256>>>(x, dd);
    k_awrite<<<dim3(8, BB), 256>>>(x, a_out);
}

// round 2
// speedup vs baseline: 1.1164x; 1.1164x over previous
#include <cuda_runtime.h>
#include <cstddef>
#include <cstdint>

// Problem constants: B=2, S=512, H=256, A=128
#define BB 2
#define SS 512
#define HH 256
#define AA 128
#define NT 32          // tiles per batch for the a-prefix
#define TS 16          // rows per tile (NT*TS == SS)

// Scratch (device globals; no allocs allowed)
__device__ float g_s[BB * SS];          // raw scores s[b,j]
__device__ float g_w[BB * SS];          // e_j * am_j
__device__ float g_scale[BB * SS];      // am_i / C_i
__device__ float g_T[BB * NT * HH];     // per-tile sums of w_j * x[b,j,:]

// ---------------------------------------------------------------------------
// Kernel 1: s[b,j] = sum_a query[a] * tanh( sum_h x[b,j,h] * w_a[h,a] )
// 8 rows per block (grid 128), 128 threads (one per a-column).
// Uses packed f32x2 FMA: 2 rows per accumulator register pair.
// ---------------------------------------------------------------------------
__global__ __launch_bounds__(128) void k_score(
    const float* __restrict__ x, const float* __restrict__ w_a,
    const float* __restrict__ query)
{
    __shared__ float xsT[HH * 8];     // transposed: xsT[h*8 + r]
    __shared__ float red[8][128];
    const int tid = threadIdx.x;
    const int r0  = blockIdx.x * 8;   // global row (b*S + j) of first row

    // load 8 rows (8*256 floats) into transposed shared layout
    const float4* xin = reinterpret_cast<const float4*>(x + (size_t)r0 * HH);
#pragma unroll
    for (int it = 0; it < 4; ++it) {
        const int idx = tid + it * 128;     // 0..511 float4 slots
        const int r   = idx & 7;
        const int h4  = idx >> 3;           // 0..63
        const float4 v = xin[r * 64 + h4];
        xsT[(h4 * 4 + 0) * 8 + r] = v.x;
        xsT[(h4 * 4 + 1) * 8 + r] = v.y;
        xsT[(h4 * 4 + 2) * 8 + r] = v.z;
        xsT[(h4 * 4 + 3) * 8 + r] = v.w;
    }
    __syncthreads();

    unsigned long long acc0 = 0ull, acc1 = 0ull, acc2 = 0ull, acc3 = 0ull;
    const float* wp = w_a + tid;
#pragma unroll 4
    for (int h = 0; h < HH; ++h) {
        const float wa = wp[h * AA];              // coalesced across threads
        unsigned long long wd;
        asm("mov.b64 %0, {%1, %1};" : "=l"(wd) : "f"(wa));
        const unsigned long long* xr =
            reinterpret_cast<const unsigned long long*>(xsT + h * 8);
        asm("fma.rn.f32x2 %0, %1, %2, %0;" : "+l"(acc0) : "l"(xr[0]), "l"(wd));
        asm("fma.rn.f32x2 %0, %1, %2, %0;" : "+l"(acc1) : "l"(xr[1]), "l"(wd));
        asm("fma.rn.f32x2 %0, %1, %2, %0;" : "+l"(acc2) : "l"(xr[2]), "l"(wd));
        asm("fma.rn.f32x2 %0, %1, %2, %0;" : "+l"(acc3) : "l"(xr[3]), "l"(wd));
    }

    const float qv = query[tid];
    unsigned long long av[4] = {acc0, acc1, acc2, acc3};
#pragma unroll
    for (int p = 0; p < 4; ++p) {
        const float lo = __uint_as_float((unsigned)(av[p] & 0xffffffffull));
        const float hi = __uint_as_float((unsigned)(av[p] >> 32));
        red[2 * p + 0][tid] = qv * tanhf(lo);
        red[2 * p + 1][tid] = qv * tanhf(hi);
    }
    __syncthreads();

    // 4 warps, each reduces 2 rows of 128 partials
    const int w = tid >> 5, l = tid & 31;
#pragma unroll
    for (int rr = 0; rr < 2; ++rr) {
        const int r = 2 * w + rr;
        float v = red[r][l] + red[r][l + 32] + red[r][l + 64] + red[r][l + 96];
#pragma unroll
        for (int o = 16; o > 0; o >>= 1) v += __shfl_down_sync(0xffffffffu, v, o);
        if (l == 0) g_s[r0 + r] = v;
    }
}

// ---------------------------------------------------------------------------
// Kernel 2: per-batch max + exp + inclusive prefix sum (shfl warp scans).
// One block per batch, 512 threads, 2 barriers.
// ---------------------------------------------------------------------------
__global__ __launch_bounds__(512) void k_scan(const int* __restrict__ amask)
{
    const int b = blockIdx.x, tid = threadIdx.x;
    const int lane = tid & 31, wid = tid >> 5;   // 16 warps
    __shared__ float wmax[16], wsum[16];

    const float sv = g_s[b * SS + tid];

    // block max
    float m = sv;
#pragma unroll
    for (int o = 16; o > 0; o >>= 1) m = fmaxf(m, __shfl_xor_sync(0xffffffffu, m, o));
    if (lane == 0) wmax[wid] = m;
    __syncthreads();
    float M = wmax[0];
#pragma unroll
    for (int k = 1; k < 16; ++k) M = fmaxf(M, wmax[k]);

    const float e = expf(sv - M);

    // inclusive warp scan
    float sc = e;
#pragma unroll
    for (int o = 1; o < 32; o <<= 1) {
        const float t = __shfl_up_sync(0xffffffffu, sc, o);
        if (lane >= o) sc += t;
    }
    if (lane == 31) wsum[wid] = sc;
    __syncthreads();
    float off = 0.f;
#pragma unroll
    for (int k = 0; k < 16; ++k)
        if (k < wid) off += wsum[k];

    const float C  = sc + off;
    const int   am = amask[b * SS + tid];
    g_w[b * SS + tid]     = am ? e : 0.f;
    g_scale[b * SS + tid] = am ? (1.f / C) : 0.f;
}

// ---------------------------------------------------------------------------
// Kernel 3: write d (B,S,S) rows AND compute NT per-tile sums
// T[b,t,h] = sum_{j in tile t} w_j * x[b,j,h].
// grid = (SS + NT, B), 256 threads.
// ---------------------------------------------------------------------------
__global__ __launch_bounds__(256) void k_dwrite(
    const float* __restrict__ x, float* __restrict__ d_out)
{
    const int b = blockIdx.y, tid = threadIdx.x;

    if (blockIdx.x < SS) {
        const int i  = blockIdx.x;
        const float sc = g_scale[b * SS + i];
        const float2 w2 = reinterpret_cast<const float2*>(g_w + b * SS)[tid];
        const int j0 = tid * 2;
        float2 o;
        o.x = (j0     <= i) ? w2.x * sc : 0.f;
        o.y = (j0 + 1 <= i) ? w2.y * sc : 0.f;
        reinterpret_cast<float2*>(d_out + (size_t)(b * SS + i) * SS)[tid] = o;
    } else {
        const int t = blockIdx.x - SS;          // 0..NT-1
        __shared__ float ws[TS];
        if (tid < TS) ws[tid] = g_w[b * SS + t * TS + tid];
        __syncthreads();
        const float* xp = x + ((size_t)(b * SS + t * TS)) * HH + tid;
        float xv[TS];
#pragma unroll
        for (int jj = 0; jj < TS; ++jj) xv[jj] = xp[(size_t)jj * HH];
        float acc = 0.f;
#pragma unroll
        for (int jj = 0; jj < TS; ++jj) acc += ws[jj] * xv[jj];
        g_T[(b * NT + t) * HH + tid] = acc;
    }
}

// ---------------------------------------------------------------------------
// Kernel 4: a[b,i,h] = scale[b,i] * ( sum of previous tile totals
//                                     + local prefix of w_j*x[b,j,h] ).
// grid = (NT, B), 256 threads (one per h). All loads batched up-front (high MLP).
// ---------------------------------------------------------------------------
__global__ __launch_bounds__(256) void k_awrite(
    const float* __restrict__ x, float* __restrict__ a_out)
{
    const int b = blockIdx.y, t = blockIdx.x, tid = threadIdx.x;
    __shared__ float ws[TS], scs[TS];
    if (tid < TS) {
        ws[tid]  = g_w[b * SS + t * TS + tid];
        scs[tid] = g_scale[b * SS + t * TS + tid];
    }
    __syncthreads();

    // batch-load this tile's 16 x-values (independent -> MLP=16)
    const float* xp = x + ((size_t)(b * SS + t * TS)) * HH + tid;
    float xv[TS];
#pragma unroll
    for (int jj = 0; jj < TS; ++jj) xv[jj] = xp[(size_t)jj * HH];

    // sum of all previous tiles' totals: fully unrolled predicated loads
    const float* Tp = g_T + (size_t)(b * NT) * HH + tid;
    float base = 0.f;
#pragma unroll
    for (int tp = 0; tp < NT - 1; ++tp)
        if (tp < t) base += Tp[(size_t)tp * HH];

    // short serial chain + stores
    float* ap = a_out + ((size_t)(b * SS + t * TS)) * HH + tid;
    float acc = base;
#pragma unroll
    for (int jj = 0; jj < TS; ++jj) {
        acc += ws[jj] * xv[jj];
        ap[(size_t)jj * HH] = acc * scs[jj];
    }
}

// ---------------------------------------------------------------------------
extern "C" void kernel_launch(void* const* d_in, const int* in_sizes, int n_in,
                              void* d_out, int out_size)
{
    const float* x     = (const float*)d_in[0];   // (B,S,H)
    const int*   amask = (const int*)  d_in[1];   // (B,S)
    const float* w_a   = (const float*)d_in[2];   // (H,A)
    const float* query = (const float*)d_in[3];   // (A,)

    float* out   = (float*)d_out;
    float* a_out = out;                                // (B,S,H) first
    float* dd    = out + (size_t)BB * SS * HH;         // (B,S,S) second

    k_score<<<(BB * SS) / 8, 128>>>(x, w_a, query);
    k_scan<<<BB, SS>>>(amask);
    k_dwrite<<<dim3(SS + NT, BB), 256>>>(x, dd);
    k_awrite<<<dim3(NT, BB), 256>>>(x, a_out);
}